// round 5
// baseline (speedup 1.0000x reference)
#include <cuda_runtime.h>
#include <cuda_bf16.h>
#include <cstdint>

#define VOCAB 32000
#define EMB   512
#define HID   1024
#define BATCH 32
#define SEQ   512
#define G4    4096
#define NTOK  (BATCH*SEQ)

// ---------------- static device scratch ----------------
__device__ float g_xproj[(size_t)NTOK * G4];            // 256 MB
__device__ uint32_t g_hpk[2][BATCH * HID];              // packed h: lo16=hi(bf16), hi16=lo(bf16)
__device__ __nv_bfloat16 g_embh[(size_t)VOCAB * EMB];   // 32 MB
__device__ __nv_bfloat16 g_embl[(size_t)VOCAB * EMB];
__device__ __nv_bfloat16 g_wihh[(size_t)G4 * EMB];      // 4 MB
__device__ __nv_bfloat16 g_wihl[(size_t)G4 * EMB];
__device__ unsigned g_bar_gen;
__device__ unsigned g_bar_cnt;

// ---------------- helpers ----------------
__device__ __forceinline__ float sigf(float v) { return 1.f / (1.f + __expf(-v)); }

__device__ __forceinline__ uint32_t pkbf(__nv_bfloat16 a, __nv_bfloat16 b) {
    __nv_bfloat162 t; t.x = a; t.y = b;
    return *(uint32_t*)&t;
}

__device__ __forceinline__ void mma_bf16(float c[4], const uint32_t a[4],
                                         uint32_t b0, uint32_t b1) {
    asm volatile(
        "mma.sync.aligned.m16n8k16.row.col.f32.bf16.bf16.f32 "
        "{%0,%1,%2,%3},{%4,%5,%6,%7},{%8,%9},{%0,%1,%2,%3};\n"
        : "+f"(c[0]), "+f"(c[1]), "+f"(c[2]), "+f"(c[3])
        : "r"(a[0]), "r"(a[1]), "r"(a[2]), "r"(a[3]), "r"(b0), "r"(b1));
}

__device__ __forceinline__ void cpa16(uint32_t dst, const void* src) {
    asm volatile("cp.async.cg.shared.global [%0], [%1], 16;" :: "r"(dst), "l"(src));
}
__device__ __forceinline__ void cpa_commit() { asm volatile("cp.async.commit_group;"); }
template<int N>
__device__ __forceinline__ void cpa_wait() { asm volatile("cp.async.wait_group %0;" :: "n"(N)); }

__device__ __forceinline__ void grid_barrier(unsigned target) {
    __syncthreads();
    if (threadIdx.x == 0) {
        __threadfence();
        unsigned prev = atomicAdd(&g_bar_cnt, 1u);
        if (prev == gridDim.x - 1) {
            atomicExch(&g_bar_cnt, 0u);
            __threadfence();
            atomicExch(&g_bar_gen, target);
        } else {
            while ((int)(*(volatile unsigned*)&g_bar_gen - target) < 0) { }
        }
        __threadfence();
    }
    __syncthreads();
}

// =====================================================================
// Kernel 0: fp32 -> bf16 hi/lo split planes
// =====================================================================
__global__ void cvt_kernel(const float* __restrict__ src,
                           __nv_bfloat16* __restrict__ hi,
                           __nv_bfloat16* __restrict__ lo, int n4) {
    for (int i = blockIdx.x * blockDim.x + threadIdx.x; i < n4;
         i += gridDim.x * blockDim.x) {
        float4 v = ((const float4*)src)[i];
        __nv_bfloat16 h0 = __float2bfloat16(v.x), h1 = __float2bfloat16(v.y);
        __nv_bfloat16 h2 = __float2bfloat16(v.z), h3 = __float2bfloat16(v.w);
        __nv_bfloat16 l0 = __float2bfloat16(v.x - __bfloat162float(h0));
        __nv_bfloat16 l1 = __float2bfloat16(v.y - __bfloat162float(h1));
        __nv_bfloat16 l2 = __float2bfloat16(v.z - __bfloat162float(h2));
        __nv_bfloat16 l3 = __float2bfloat16(v.w - __bfloat162float(h3));
        ((uint2*)hi)[i] = make_uint2(pkbf(h0, h1), pkbf(h2, h3));
        ((uint2*)lo)[i] = make_uint2(pkbf(l0, l1), pkbf(l2, l3));
    }
}

// =====================================================================
// Kernel 1: x_proj via bf16 split tensor-core GEMM.
// Block 128x128xK32, 256 thr (8 warps 2x4, warp 64x32), cp.async dbuf.
// =====================================================================
#define XBM 128
#define XBN 128
#define XBK 32
#define XLDA 40                      // bf16 per smem row (pad: conflict-free)
#define XPLANE (XBM * XLDA)          // 5120 bf16 per plane
#define XBUF (4 * XPLANE)            // Ah,Al,Bh,Bl
#define XKT (EMB / XBK)              // 16

__global__ void __launch_bounds__(256, 2) xproj_kernel(
    const int* __restrict__ x,
    const float* __restrict__ bih,
    const float* __restrict__ bhh)
{
    extern __shared__ __nv_bfloat16 xsm[];   // [2][4][128][XLDA]
    const uint32_t smem_u32 = (uint32_t)__cvta_generic_to_shared(xsm);

    const int tid  = threadIdx.x;
    const int lane = tid & 31;
    const int wid  = tid >> 5;
    const int m0 = blockIdx.y * XBM;
    const int n0 = blockIdx.x * XBN;

    // loaders: 2 thr/row, 16 bf16 (32B) each
    const int lrow = tid >> 1;
    const int lk   = (tid & 1) * 16;
    int erow = x[m0 + lrow];
    erow = max(0, min(VOCAB - 1, erow));
    const __nv_bfloat16* ah_src = g_embh + (size_t)erow * EMB + lk;
    const __nv_bfloat16* al_src = g_embl + (size_t)erow * EMB + lk;
    const __nv_bfloat16* bh_src = g_wihh + (size_t)(n0 + lrow) * EMB + lk;
    const __nv_bfloat16* bl_src = g_wihl + (size_t)(n0 + lrow) * EMB + lk;
    const uint32_t dA = smem_u32 + (uint32_t)(lrow * XLDA + lk) * 2;
    const uint32_t dB = dA + 2 * XPLANE * 2;

    const int wm = (wid >> 2) * 64;
    const int wn = (wid & 3) * 32;
    const int lr = lane >> 2;
    const int lc = lane & 3;

    float acc[4][4][4];
#pragma unroll
    for (int mt = 0; mt < 4; mt++)
#pragma unroll
        for (int nt = 0; nt < 4; nt++)
#pragma unroll
            for (int q = 0; q < 4; q++) acc[mt][nt][q] = 0.f;

    auto issue = [&](int it) {
        const uint32_t bo = (uint32_t)((it & 1) * XBUF) * 2;
        const int ko = it * XBK;
        cpa16(dA + bo,                   ah_src + ko);
        cpa16(dA + bo + 16,              ah_src + ko + 8);
        cpa16(dA + bo + XPLANE * 2,      al_src + ko);
        cpa16(dA + bo + XPLANE * 2 + 16, al_src + ko + 8);
        cpa16(dB + bo,                   bh_src + ko);
        cpa16(dB + bo + 16,              bh_src + ko + 8);
        cpa16(dB + bo + XPLANE * 2,      bl_src + ko);
        cpa16(dB + bo + XPLANE * 2 + 16, bl_src + ko + 8);
    };

    issue(0); cpa_commit();

    for (int it = 0; it < XKT; ++it) {
        if (it < XKT - 1) { issue(it + 1); cpa_commit(); cpa_wait<1>(); }
        else              { cpa_wait<0>(); }
        __syncthreads();

        const __nv_bfloat16* Ah = xsm + (it & 1) * XBUF;
        const __nv_bfloat16* Al = Ah + XPLANE;
        const __nv_bfloat16* Bh = Al + XPLANE;
        const __nv_bfloat16* Bl = Bh + XPLANE;

#pragma unroll
        for (int ksi = 0; ksi < 2; ++ksi) {
            const int ks = ksi * 16;
            // cache B fragments for the 4 n-tiles
            uint32_t bfh[4][2], bfl[4][2];
#pragma unroll
            for (int nt = 0; nt < 4; ++nt) {
                const int bi = (wn + nt * 8 + lr) * XLDA + ks + lc * 2;
                bfh[nt][0] = *(const uint32_t*)(Bh + bi);
                bfh[nt][1] = *(const uint32_t*)(Bh + bi + 8);
                bfl[nt][0] = *(const uint32_t*)(Bl + bi);
                bfl[nt][1] = *(const uint32_t*)(Bl + bi + 8);
            }
#pragma unroll
            for (int mt = 0; mt < 4; ++mt) {
                const int ai = (wm + mt * 16 + lr) * XLDA + ks + lc * 2;
                uint32_t afh[4], afl[4];
                afh[0] = *(const uint32_t*)(Ah + ai);
                afh[1] = *(const uint32_t*)(Ah + ai + 8 * XLDA);
                afh[2] = *(const uint32_t*)(Ah + ai + 8);
                afh[3] = *(const uint32_t*)(Ah + ai + 8 * XLDA + 8);
                afl[0] = *(const uint32_t*)(Al + ai);
                afl[1] = *(const uint32_t*)(Al + ai + 8 * XLDA);
                afl[2] = *(const uint32_t*)(Al + ai + 8);
                afl[3] = *(const uint32_t*)(Al + ai + 8 * XLDA + 8);
#pragma unroll
                for (int nt = 0; nt < 4; ++nt) {
                    mma_bf16(acc[mt][nt], afh, bfh[nt][0], bfh[nt][1]);
                    mma_bf16(acc[mt][nt], afh, bfl[nt][0], bfl[nt][1]);
                    mma_bf16(acc[mt][nt], afl, bfh[nt][0], bfh[nt][1]);
                }
            }
        }
        __syncthreads();
    }

    // epilogue: bias + fp32 store
    float bias0[4], bias1[4];
#pragma unroll
    for (int nt = 0; nt < 4; ++nt) {
        const int n_g = n0 + wn + nt * 8 + lc * 2;
        bias0[nt] = bih[n_g] + bhh[n_g];
        bias1[nt] = bih[n_g + 1] + bhh[n_g + 1];
    }
#pragma unroll
    for (int mt = 0; mt < 4; ++mt) {
        const int m_g = m0 + wm + mt * 16 + lr;
#pragma unroll
        for (int nt = 0; nt < 4; ++nt) {
            const int n_g = n0 + wn + nt * 8 + lc * 2;
            float2 r0, r1;
            r0.x = acc[mt][nt][0] + bias0[nt];
            r0.y = acc[mt][nt][1] + bias1[nt];
            r1.x = acc[mt][nt][2] + bias0[nt];
            r1.y = acc[mt][nt][3] + bias1[nt];
            *(float2*)&g_xproj[(size_t)m_g * G4 + n_g]       = r0;
            *(float2*)&g_xproj[(size_t)(m_g + 8) * G4 + n_g] = r1;
        }
    }
}

// =====================================================================
// Kernel 2: persistent tensor-core LSTM. 128 blocks x 512 thr (16 warps).
// Block owns 8 hidden units -> 32 gate rows (M). W_hh fragments live in
// registers (bf16 hi/lo). h = B operand, packed global -> smem per step.
// Warps: 8 kgroups (K=128) x 2 m-tiles. Smem reduce over kgroups.
// =====================================================================
#define RT   512
#define HLD  1036                     // words per h row in smem (pad)
#define RLD  34                       // reduce row pad

__global__ void __launch_bounds__(RT, 1) lstm_kernel(
    const float* __restrict__ Whh,
    float* __restrict__ out,
    int out_size)
{
    extern __shared__ uint32_t lsm[];
    uint32_t* h_s = lsm;                          // [32][HLD]
    float* red = (float*)(lsm + 32 * HLD);        // [8][32][RLD]

    const int tid  = threadIdx.x;
    const int lane = tid & 31;
    const int wid  = tid >> 5;
    const int kg   = wid >> 1;        // 0..7
    const int mt   = wid & 1;         // 0..1
    const int lr   = lane >> 2;
    const int lc   = lane & 3;
    const int j0   = blockIdx.x * 8;

    const unsigned gen0 = *(volatile unsigned*)&g_bar_gen;

    // ---- preload W_hh fragments into registers ----
    uint32_t ah[8][4], al[8][4];
#pragma unroll
    for (int s = 0; s < 8; ++s) {
#pragma unroll
        for (int r = 0; r < 4; ++r) {
            const int row = mt * 16 + lr + (r & 1) * 8;      // 0..31
            const int kk  = kg * 128 + s * 16 + lc * 2 + (r >> 1) * 8;
            const int q = row >> 3, jl = row & 7;
            float2 w = *(const float2*)(Whh + (size_t)(q * HID + j0 + jl) * HID + kk);
            __nv_bfloat16 h0 = __float2bfloat16(w.x);
            __nv_bfloat16 h1 = __float2bfloat16(w.y);
            __nv_bfloat16 l0 = __float2bfloat16(w.x - __bfloat162float(h0));
            __nv_bfloat16 l1 = __float2bfloat16(w.y - __bfloat162float(h1));
            ah[s][r] = pkbf(h0, h1);
            al[s][r] = pkbf(l0, l1);
        }
    }

    // epilogue ownership: tid<256 -> (b, jl)
    const bool owner = (tid < 256);
    const int b_e  = tid >> 3;        // 0..31
    const int jl_e = tid & 7;
    const int jg   = j0 + jl_e;

    float c_reg = 0.f;
    float xpi = 0.f, xpf = 0.f, xpg = 0.f, xpo = 0.f;

    // ---- t = 0 ----
    if (owner) {
        const float* xp = g_xproj + (size_t)b_e * SEQ * G4;
        float iv = sigf(xp[jg]);
        float gv = tanhf(xp[2 * HID + jg]);
        float ov = sigf(xp[3 * HID + jg]);
        c_reg = iv * gv;
        float hv = ov * tanhf(c_reg);
        out[(size_t)b_e * SEQ * HID + jg] = hv;
        __nv_bfloat16 hh = __float2bfloat16(hv);
        __nv_bfloat16 hl = __float2bfloat16(hv - __bfloat162float(hh));
        g_hpk[1][b_e * HID + jg] = pkbf(hh, hl);
        // prefetch x_proj for t=1
        const float* xp1 = xp + G4;
        xpi = xp1[jg]; xpf = xp1[HID + jg];
        xpg = xp1[2 * HID + jg]; xpo = xp1[3 * HID + jg];
    }
    grid_barrier(gen0 + 1);

    // ---- t = 1 .. 511 ----
    for (int t = 1; t < SEQ; ++t) {
        // stage packed h: 8192 uint4 over 512 threads (16 each)
        {
            const uint4* src = ((const uint4*)g_hpk[t & 1]) + (size_t)tid * 16;
            uint32_t* dst = h_s + (tid >> 4) * HLD + (tid & 15) * 64;
            uint4 tmp[8];
#pragma unroll
            for (int i = 0; i < 8; ++i) tmp[i] = __ldcg(src + i);
#pragma unroll
            for (int i = 0; i < 8; ++i) *(uint4*)(dst + i * 4) = tmp[i];
#pragma unroll
            for (int i = 0; i < 8; ++i) tmp[i] = __ldcg(src + 8 + i);
#pragma unroll
            for (int i = 0; i < 8; ++i) *(uint4*)(dst + 32 + i * 4) = tmp[i];
        }
        __syncthreads();

        float acc[4][4];
#pragma unroll
        for (int nt = 0; nt < 4; nt++)
#pragma unroll
            for (int q = 0; q < 4; q++) acc[nt][q] = 0.f;

#pragma unroll
        for (int s = 0; s < 8; ++s) {
#pragma unroll
            for (int nt = 0; nt < 4; ++nt) {
                const uint32_t* hp = h_s + (nt * 8 + lr) * HLD + kg * 128 + s * 16 + lc * 2;
                uint32_t w0 = hp[0], w1 = hp[1], w2 = hp[8], w3 = hp[9];
                uint32_t bh0 = __byte_perm(w0, w1, 0x5410);
                uint32_t bl0 = __byte_perm(w0, w1, 0x7632);
                uint32_t bh1 = __byte_perm(w2, w3, 0x5410);
                uint32_t bl1 = __byte_perm(w2, w3, 0x7632);
                mma_bf16(acc[nt], ah[s], bh0, bh1);
                mma_bf16(acc[nt], ah[s], bl0, bl1);
                mma_bf16(acc[nt], al[s], bh0, bh1);
            }
        }

        // stage partial sums: red[kg][m][n]
#pragma unroll
        for (int nt = 0; nt < 4; ++nt) {
            float* rp = red + (size_t)(kg * 32 + mt * 16 + lr) * RLD + nt * 8 + lc * 2;
            rp[0] = acc[nt][0]; rp[1] = acc[nt][1];
            rp[8 * RLD] = acc[nt][2]; rp[8 * RLD + 1] = acc[nt][3];
        }
        __syncthreads();

        if (owner) {
            float g0 = xpi, g1 = xpf, g2 = xpg, g3 = xpo;
#pragma unroll
            for (int k = 0; k < 8; ++k) {
                const float* rp = red + (size_t)(k * 32 + jl_e) * RLD + b_e;
                g0 += rp[0];
                g1 += rp[8 * RLD];
                g2 += rp[16 * RLD];
                g3 += rp[24 * RLD];
            }
            const float iv = sigf(g0);
            const float fv = sigf(g1);
            const float gv = tanhf(g2);
            const float ov = sigf(g3);
            c_reg = fv * c_reg + iv * gv;
            const float hv = ov * tanhf(c_reg);

            out[((size_t)b_e * SEQ + t) * HID + jg] = hv;
            __nv_bfloat16 hh = __float2bfloat16(hv);
            __nv_bfloat16 hl = __float2bfloat16(hv - __bfloat162float(hh));
            g_hpk[(t + 1) & 1][b_e * HID + jg] = pkbf(hh, hl);

            if (t == SEQ - 1) {
                if (out_size >= NTOK * HID + 2 * BATCH * HID) {
                    float* sh = out + (size_t)NTOK * HID;
                    float* sc = sh + (size_t)BATCH * HID;
                    sh[(size_t)b_e * HID + jg] = hv;
                    sc[(size_t)b_e * HID + jg] = c_reg;
                }
            } else {
                const float* xp = g_xproj + ((size_t)b_e * SEQ + t + 1) * G4;
                xpi = xp[jg]; xpf = xp[HID + jg];
                xpg = xp[2 * HID + jg]; xpo = xp[3 * HID + jg];
            }
        }
        if (t < SEQ - 1) grid_barrier(gen0 + 1 + t);
    }
}

// =====================================================================
extern "C" void kernel_launch(void* const* d_in, const int* in_sizes, int n_in,
                              void* d_out, int out_size)
{
    (void)in_sizes; (void)n_in;
    const int*   x   = (const int*)d_in[0];
    const float* emb = (const float*)d_in[1];
    const float* Wih = (const float*)d_in[2];
    const float* Whh = (const float*)d_in[3];
    const float* bih = (const float*)d_in[4];
    const float* bhh = (const float*)d_in[5];
    float*       out = (float*)d_out;

    // resolve device-global scratch addresses (host side, graph-safe)
    static __nv_bfloat16 *p_embh = nullptr, *p_embl, *p_wihh, *p_wihl;
    if (!p_embh) {
        cudaGetSymbolAddress((void**)&p_embh, g_embh);
        cudaGetSymbolAddress((void**)&p_embl, g_embl);
        cudaGetSymbolAddress((void**)&p_wihh, g_wihh);
        cudaGetSymbolAddress((void**)&p_wihl, g_wihl);
    }

    cvt_kernel<<<2048, 256>>>(emb, p_embh, p_embl, VOCAB * EMB / 4);
    cvt_kernel<<<512, 256>>>(Wih, p_wihh, p_wihl, G4 * EMB / 4);

    const int xsmem = 2 * XBUF * (int)sizeof(__nv_bfloat16);            // 81920 B
    cudaFuncSetAttribute(xproj_kernel, cudaFuncAttributeMaxDynamicSharedMemorySize, xsmem);
    dim3 g1(G4 / XBN, NTOK / XBM);
    xproj_kernel<<<g1, 256, xsmem>>>(x, bih, bhh);

    const int lsmem = (32 * HLD + 8 * 32 * RLD) * (int)sizeof(uint32_t); // 167424 B
    cudaFuncSetAttribute(lstm_kernel, cudaFuncAttributeMaxDynamicSharedMemorySize, lsmem);
    lstm_kernel<<<128, RT, lsmem>>>(Whh, out, out_size);
}

// round 6
// speedup vs baseline: 1.6280x; 1.6280x over previous
#include <cuda_runtime.h>
#include <cuda_bf16.h>
#include <cstdint>

#define VOCAB 32000
#define EMB   512
#define HID   1024
#define BATCH 32
#define SEQ   512
#define G4    4096
#define NTOK  (BATCH*SEQ)

// ---------------- static device scratch ----------------
__device__ float g_xproj[(size_t)NTOK * G4];            // 256 MB
__device__ uint32_t g_hpk[2][BATCH * HID];              // packed h: lo16=hi(bf16), hi16=lo(bf16)
__device__ __nv_bfloat16 g_embh[(size_t)VOCAB * EMB];   // 32 MB
__device__ __nv_bfloat16 g_embl[(size_t)VOCAB * EMB];
__device__ __nv_bfloat16 g_wihh[(size_t)G4 * EMB];      // 4 MB
__device__ __nv_bfloat16 g_wihl[(size_t)G4 * EMB];
__device__ unsigned g_bar_gen;
__device__ unsigned g_bar_cnt;

// ---------------- helpers ----------------
__device__ __forceinline__ float sigf(float v) { return 1.f / (1.f + __expf(-v)); }

__device__ __forceinline__ uint32_t pkbf(__nv_bfloat16 a, __nv_bfloat16 b) {
    __nv_bfloat162 t; t.x = a; t.y = b;
    return *(uint32_t*)&t;
}

__device__ __forceinline__ void mma_bf16(float c[4], const uint32_t a[4],
                                         uint32_t b0, uint32_t b1) {
    asm volatile(
        "mma.sync.aligned.m16n8k16.row.col.f32.bf16.bf16.f32 "
        "{%0,%1,%2,%3},{%4,%5,%6,%7},{%8,%9},{%0,%1,%2,%3};\n"
        : "+f"(c[0]), "+f"(c[1]), "+f"(c[2]), "+f"(c[3])
        : "r"(a[0]), "r"(a[1]), "r"(a[2]), "r"(a[3]), "r"(b0), "r"(b1));
}

__device__ __forceinline__ void cpa16(uint32_t dst, const void* src) {
    asm volatile("cp.async.cg.shared.global [%0], [%1], 16;" :: "r"(dst), "l"(src));
}
__device__ __forceinline__ void cpa_commit() { asm volatile("cp.async.commit_group;"); }
template<int N>
__device__ __forceinline__ void cpa_wait() { asm volatile("cp.async.wait_group %0;" :: "n"(N)); }

__device__ __forceinline__ void grid_barrier(unsigned target) {
    __syncthreads();
    if (threadIdx.x == 0) {
        __threadfence();
        unsigned prev = atomicAdd(&g_bar_cnt, 1u);
        if (prev == gridDim.x - 1) {
            atomicExch(&g_bar_cnt, 0u);
            __threadfence();
            atomicExch(&g_bar_gen, target);
        } else {
            while ((int)(*(volatile unsigned*)&g_bar_gen - target) < 0) { }
        }
        __threadfence();
    }
    __syncthreads();
}

// =====================================================================
// Kernel 0: fp32 -> bf16 hi/lo split planes
// =====================================================================
__global__ void cvt_kernel(const float* __restrict__ src,
                           __nv_bfloat16* __restrict__ hi,
                           __nv_bfloat16* __restrict__ lo, int n4) {
    for (int i = blockIdx.x * blockDim.x + threadIdx.x; i < n4;
         i += gridDim.x * blockDim.x) {
        float4 v = ((const float4*)src)[i];
        __nv_bfloat16 h0 = __float2bfloat16(v.x), h1 = __float2bfloat16(v.y);
        __nv_bfloat16 h2 = __float2bfloat16(v.z), h3 = __float2bfloat16(v.w);
        __nv_bfloat16 l0 = __float2bfloat16(v.x - __bfloat162float(h0));
        __nv_bfloat16 l1 = __float2bfloat16(v.y - __bfloat162float(h1));
        __nv_bfloat16 l2 = __float2bfloat16(v.z - __bfloat162float(h2));
        __nv_bfloat16 l3 = __float2bfloat16(v.w - __bfloat162float(h3));
        ((uint2*)hi)[i] = make_uint2(pkbf(h0, h1), pkbf(h2, h3));
        ((uint2*)lo)[i] = make_uint2(pkbf(l0, l1), pkbf(l2, l3));
    }
}

// =====================================================================
// Kernel 1: x_proj via bf16 split tensor-core GEMM (unchanged, round 5).
// =====================================================================
#define XBM 128
#define XBN 128
#define XBK 32
#define XLDA 40
#define XPLANE (XBM * XLDA)
#define XBUF (4 * XPLANE)
#define XKT (EMB / XBK)

__global__ void __launch_bounds__(256, 2) xproj_kernel(
    const int* __restrict__ x,
    const float* __restrict__ bih,
    const float* __restrict__ bhh)
{
    extern __shared__ __nv_bfloat16 xsm[];
    const uint32_t smem_u32 = (uint32_t)__cvta_generic_to_shared(xsm);

    const int tid  = threadIdx.x;
    const int lane = tid & 31;
    const int wid  = tid >> 5;
    const int m0 = blockIdx.y * XBM;
    const int n0 = blockIdx.x * XBN;

    const int lrow = tid >> 1;
    const int lk   = (tid & 1) * 16;
    int erow = x[m0 + lrow];
    erow = max(0, min(VOCAB - 1, erow));
    const __nv_bfloat16* ah_src = g_embh + (size_t)erow * EMB + lk;
    const __nv_bfloat16* al_src = g_embl + (size_t)erow * EMB + lk;
    const __nv_bfloat16* bh_src = g_wihh + (size_t)(n0 + lrow) * EMB + lk;
    const __nv_bfloat16* bl_src = g_wihl + (size_t)(n0 + lrow) * EMB + lk;
    const uint32_t dA = smem_u32 + (uint32_t)(lrow * XLDA + lk) * 2;
    const uint32_t dB = dA + 2 * XPLANE * 2;

    const int wm = (wid >> 2) * 64;
    const int wn = (wid & 3) * 32;
    const int lr = lane >> 2;
    const int lc = lane & 3;

    float acc[4][4][4];
#pragma unroll
    for (int mt = 0; mt < 4; mt++)
#pragma unroll
        for (int nt = 0; nt < 4; nt++)
#pragma unroll
            for (int q = 0; q < 4; q++) acc[mt][nt][q] = 0.f;

    auto issue = [&](int it) {
        const uint32_t bo = (uint32_t)((it & 1) * XBUF) * 2;
        const int ko = it * XBK;
        cpa16(dA + bo,                   ah_src + ko);
        cpa16(dA + bo + 16,              ah_src + ko + 8);
        cpa16(dA + bo + XPLANE * 2,      al_src + ko);
        cpa16(dA + bo + XPLANE * 2 + 16, al_src + ko + 8);
        cpa16(dB + bo,                   bh_src + ko);
        cpa16(dB + bo + 16,              bh_src + ko + 8);
        cpa16(dB + bo + XPLANE * 2,      bl_src + ko);
        cpa16(dB + bo + XPLANE * 2 + 16, bl_src + ko + 8);
    };

    issue(0); cpa_commit();

    for (int it = 0; it < XKT; ++it) {
        if (it < XKT - 1) { issue(it + 1); cpa_commit(); cpa_wait<1>(); }
        else              { cpa_wait<0>(); }
        __syncthreads();

        const __nv_bfloat16* Ah = xsm + (it & 1) * XBUF;
        const __nv_bfloat16* Al = Ah + XPLANE;
        const __nv_bfloat16* Bh = Al + XPLANE;
        const __nv_bfloat16* Bl = Bh + XPLANE;

#pragma unroll
        for (int ksi = 0; ksi < 2; ++ksi) {
            const int ks = ksi * 16;
            uint32_t bfh[4][2], bfl[4][2];
#pragma unroll
            for (int nt = 0; nt < 4; ++nt) {
                const int bi = (wn + nt * 8 + lr) * XLDA + ks + lc * 2;
                bfh[nt][0] = *(const uint32_t*)(Bh + bi);
                bfh[nt][1] = *(const uint32_t*)(Bh + bi + 8);
                bfl[nt][0] = *(const uint32_t*)(Bl + bi);
                bfl[nt][1] = *(const uint32_t*)(Bl + bi + 8);
            }
#pragma unroll
            for (int mt = 0; mt < 4; ++mt) {
                const int ai = (wm + mt * 16 + lr) * XLDA + ks + lc * 2;
                uint32_t afh[4], afl[4];
                afh[0] = *(const uint32_t*)(Ah + ai);
                afh[1] = *(const uint32_t*)(Ah + ai + 8 * XLDA);
                afh[2] = *(const uint32_t*)(Ah + ai + 8);
                afh[3] = *(const uint32_t*)(Ah + ai + 8 * XLDA + 8);
                afl[0] = *(const uint32_t*)(Al + ai);
                afl[1] = *(const uint32_t*)(Al + ai + 8 * XLDA);
                afl[2] = *(const uint32_t*)(Al + ai + 8);
                afl[3] = *(const uint32_t*)(Al + ai + 8 * XLDA + 8);
#pragma unroll
                for (int nt = 0; nt < 4; ++nt) {
                    mma_bf16(acc[mt][nt], afh, bfh[nt][0], bfh[nt][1]);
                    mma_bf16(acc[mt][nt], afh, bfl[nt][0], bfl[nt][1]);
                    mma_bf16(acc[mt][nt], afl, bfh[nt][0], bfh[nt][1]);
                }
            }
        }
        __syncthreads();
    }

    float bias0[4], bias1[4];
#pragma unroll
    for (int nt = 0; nt < 4; ++nt) {
        const int n_g = n0 + wn + nt * 8 + lc * 2;
        bias0[nt] = bih[n_g] + bhh[n_g];
        bias1[nt] = bih[n_g + 1] + bhh[n_g + 1];
    }
#pragma unroll
    for (int mt = 0; mt < 4; ++mt) {
        const int m_g = m0 + wm + mt * 16 + lr;
#pragma unroll
        for (int nt = 0; nt < 4; ++nt) {
            const int n_g = n0 + wn + nt * 8 + lc * 2;
            float2 r0, r1;
            r0.x = acc[mt][nt][0] + bias0[nt];
            r0.y = acc[mt][nt][1] + bias1[nt];
            r1.x = acc[mt][nt][2] + bias0[nt];
            r1.y = acc[mt][nt][3] + bias1[nt];
            *(float2*)&g_xproj[(size_t)m_g * G4 + n_g]       = r0;
            *(float2*)&g_xproj[(size_t)(m_g + 8) * G4 + n_g] = r1;
        }
    }
}

// =====================================================================
// Kernel 2: persistent tensor-core LSTM (round 6 rework).
// 128 blocks x 512 thr. W_hh bf16 hi/lo fragments in registers (64 regs).
// h staged via cp.async (coalesced, zero regs), split in two K-halves:
// warps kg<4 compute after half0 lands, kg>=4 after half1.
// =====================================================================
#define RT   512
#define HLD  1036                     // words per h row in smem (pad)
#define RLD  34                       // reduce row pad

__global__ void __launch_bounds__(RT, 1) lstm_kernel(
    const float* __restrict__ Whh,
    float* __restrict__ out,
    int out_size)
{
    extern __shared__ uint32_t lsm[];
    uint32_t* h_s = lsm;                          // [32][HLD]
    float* red = (float*)(lsm + 32 * HLD);        // [8][32][RLD]
    const uint32_t hbase = (uint32_t)__cvta_generic_to_shared(lsm);

    const int tid  = threadIdx.x;
    const int lane = tid & 31;
    const int wid  = tid >> 5;
    const int kg   = wid >> 1;        // 0..7 (K-group of 128)
    const int mt   = wid & 1;         // 0..1 (M-tile of 16)
    const int lr   = lane >> 2;
    const int lc   = lane & 3;
    const int j0   = blockIdx.x * 8;

    const unsigned gen0 = *(volatile unsigned*)&g_bar_gen;

    // ---- preload W_hh fragments into registers (stay resident) ----
    uint32_t ah[8][4], al[8][4];
#pragma unroll
    for (int s = 0; s < 8; ++s) {
#pragma unroll
        for (int r = 0; r < 4; ++r) {
            const int row = mt * 16 + lr + (r & 1) * 8;      // 0..31
            const int kk  = kg * 128 + s * 16 + lc * 2 + (r >> 1) * 8;
            const int q = row >> 3, jl = row & 7;
            float2 w = *(const float2*)(Whh + (size_t)(q * HID + j0 + jl) * HID + kk);
            __nv_bfloat16 h0 = __float2bfloat16(w.x);
            __nv_bfloat16 h1 = __float2bfloat16(w.y);
            __nv_bfloat16 l0 = __float2bfloat16(w.x - __bfloat162float(h0));
            __nv_bfloat16 l1 = __float2bfloat16(w.y - __bfloat162float(h1));
            ah[s][r] = pkbf(h0, h1);
            al[s][r] = pkbf(l0, l1);
        }
    }

    // epilogue ownership: tid<256 -> (b, jl)
    const bool owner = (tid < 256);
    const int b_e  = tid >> 3;        // 0..31
    const int jl_e = tid & 7;
    const int jg   = j0 + jl_e;

    float c_reg = 0.f;
    float xpi = 0.f, xpf = 0.f, xpg = 0.f, xpo = 0.f;

    // ---- t = 0 ----
    if (owner) {
        const float* xp = g_xproj + (size_t)b_e * SEQ * G4;
        float iv = sigf(xp[jg]);
        float gv = tanhf(xp[2 * HID + jg]);
        float ov = sigf(xp[3 * HID + jg]);
        c_reg = iv * gv;
        float hv = ov * tanhf(c_reg);
        out[(size_t)b_e * SEQ * HID + jg] = hv;
        __nv_bfloat16 hh = __float2bfloat16(hv);
        __nv_bfloat16 hl = __float2bfloat16(hv - __bfloat162float(hh));
        g_hpk[1][b_e * HID + jg] = pkbf(hh, hl);
        const float* xp1 = xp + G4;
        xpi = xp1[jg]; xpf = xp1[HID + jg];
        xpg = xp1[2 * HID + jg]; xpo = xp1[3 * HID + jg];
    }
    grid_barrier(gen0 + 1);

    // ---- t = 1 .. 511 ----
    for (int t = 1; t < SEQ; ++t) {
        // ---- stage packed h via cp.async, split in two K-halves ----
        {
            const uint4* src = (const uint4*)g_hpk[t & 1];
#pragma unroll
            for (int i = 0; i < 8; ++i) {
                const int idx = tid + i * RT;           // 0..4095
                const int b  = idx >> 7;                // batch
                const int k4 = idx & 127;               // uint4 within half
                cpa16(hbase + (uint32_t)(b * HLD + k4 * 4) * 4,
                      src + b * 256 + k4);              // half0: K[0:512)
            }
            cpa_commit();
#pragma unroll
            for (int i = 0; i < 8; ++i) {
                const int idx = tid + i * RT;
                const int b  = idx >> 7;
                const int k4 = idx & 127;
                cpa16(hbase + (uint32_t)(b * HLD + 512 + k4 * 4) * 4,
                      src + b * 256 + 128 + k4);        // half1: K[512:1024)
            }
            cpa_commit();
        }

        float acc[4][4];
#pragma unroll
        for (int nt = 0; nt < 4; nt++)
#pragma unroll
            for (int q = 0; q < 4; q++) acc[nt][q] = 0.f;

        cpa_wait<1>();
        __syncthreads();                // half0 visible to all

        if (kg < 4) {                   // K-slice within half0
#pragma unroll
            for (int s = 0; s < 8; ++s) {
#pragma unroll
                for (int nt = 0; nt < 4; ++nt) {
                    const uint32_t* hp = h_s + (nt * 8 + lr) * HLD + kg * 128 + s * 16 + lc * 2;
                    uint32_t w0 = hp[0], w1 = hp[1], w2 = hp[8], w3 = hp[9];
                    uint32_t bh0 = __byte_perm(w0, w1, 0x5410);
                    uint32_t bl0 = __byte_perm(w0, w1, 0x7632);
                    uint32_t bh1 = __byte_perm(w2, w3, 0x5410);
                    uint32_t bl1 = __byte_perm(w2, w3, 0x7632);
                    mma_bf16(acc[nt], ah[s], bh0, bh1);
                    mma_bf16(acc[nt], ah[s], bl0, bl1);
                    mma_bf16(acc[nt], al[s], bh0, bh1);
                }
            }
        }

        cpa_wait<0>();
        __syncthreads();                // half1 visible to all

        if (kg >= 4) {                  // K-slice within half1
#pragma unroll
            for (int s = 0; s < 8; ++s) {
#pragma unroll
                for (int nt = 0; nt < 4; ++nt) {
                    const uint32_t* hp = h_s + (nt * 8 + lr) * HLD + kg * 128 + s * 16 + lc * 2;
                    uint32_t w0 = hp[0], w1 = hp[1], w2 = hp[8], w3 = hp[9];
                    uint32_t bh0 = __byte_perm(w0, w1, 0x5410);
                    uint32_t bl0 = __byte_perm(w0, w1, 0x7632);
                    uint32_t bh1 = __byte_perm(w2, w3, 0x5410);
                    uint32_t bl1 = __byte_perm(w2, w3, 0x7632);
                    mma_bf16(acc[nt], ah[s], bh0, bh1);
                    mma_bf16(acc[nt], ah[s], bl0, bl1);
                    mma_bf16(acc[nt], al[s], bh0, bh1);
                }
            }
        }

        // stage partial sums: red[kg][row][n]
#pragma unroll
        for (int nt = 0; nt < 4; ++nt) {
            float* rp = red + (size_t)(kg * 32 + mt * 16 + lr) * RLD + nt * 8 + lc * 2;
            rp[0] = acc[nt][0]; rp[1] = acc[nt][1];
            rp[8 * RLD] = acc[nt][2]; rp[8 * RLD + 1] = acc[nt][3];
        }
        __syncthreads();

        if (owner) {
            float g0 = xpi, g1 = xpf, g2 = xpg, g3 = xpo;
#pragma unroll
            for (int k = 0; k < 8; ++k) {
                const float* rp = red + (size_t)(k * 32 + jl_e) * RLD + b_e;
                g0 += rp[0];
                g1 += rp[8 * RLD];
                g2 += rp[16 * RLD];
                g3 += rp[24 * RLD];
            }
            const float iv = sigf(g0);
            const float fv = sigf(g1);
            const float gv = tanhf(g2);
            const float ov = sigf(g3);
            c_reg = fv * c_reg + iv * gv;
            const float hv = ov * tanhf(c_reg);

            out[((size_t)b_e * SEQ + t) * HID + jg] = hv;
            __nv_bfloat16 hh = __float2bfloat16(hv);
            __nv_bfloat16 hl = __float2bfloat16(hv - __bfloat162float(hh));
            g_hpk[(t + 1) & 1][b_e * HID + jg] = pkbf(hh, hl);

            if (t == SEQ - 1) {
                if (out_size >= NTOK * HID + 2 * BATCH * HID) {
                    float* sh = out + (size_t)NTOK * HID;
                    float* sc = sh + (size_t)BATCH * HID;
                    sh[(size_t)b_e * HID + jg] = hv;
                    sc[(size_t)b_e * HID + jg] = c_reg;
                }
            } else {
                const float* xp = g_xproj + ((size_t)b_e * SEQ + t + 1) * G4;
                xpi = xp[jg]; xpf = xp[HID + jg];
                xpg = xp[2 * HID + jg]; xpo = xp[3 * HID + jg];
            }
        }
        if (t < SEQ - 1) grid_barrier(gen0 + 1 + t);
    }
}

// =====================================================================
extern "C" void kernel_launch(void* const* d_in, const int* in_sizes, int n_in,
                              void* d_out, int out_size)
{
    (void)in_sizes; (void)n_in;
    const int*   x   = (const int*)d_in[0];
    const float* emb = (const float*)d_in[1];
    const float* Wih = (const float*)d_in[2];
    const float* Whh = (const float*)d_in[3];
    const float* bih = (const float*)d_in[4];
    const float* bhh = (const float*)d_in[5];
    float*       out = (float*)d_out;

    static __nv_bfloat16 *p_embh = nullptr, *p_embl, *p_wihh, *p_wihl;
    if (!p_embh) {
        cudaGetSymbolAddress((void**)&p_embh, g_embh);
        cudaGetSymbolAddress((void**)&p_embl, g_embl);
        cudaGetSymbolAddress((void**)&p_wihh, g_wihh);
        cudaGetSymbolAddress((void**)&p_wihl, g_wihl);
    }

    cvt_kernel<<<2048, 256>>>(emb, p_embh, p_embl, VOCAB * EMB / 4);
    cvt_kernel<<<512, 256>>>(Wih, p_wihh, p_wihl, G4 * EMB / 4);

    const int xsmem = 2 * XBUF * (int)sizeof(__nv_bfloat16);            // 81920 B
    cudaFuncSetAttribute(xproj_kernel, cudaFuncAttributeMaxDynamicSharedMemorySize, xsmem);
    dim3 g1(G4 / XBN, NTOK / XBM);
    xproj_kernel<<<g1, 256, xsmem>>>(x, bih, bhh);

    const int lsmem = (32 * HLD + 8 * 32 * RLD) * (int)sizeof(uint32_t); // 167424 B
    cudaFuncSetAttribute(lstm_kernel, cudaFuncAttributeMaxDynamicSharedMemorySize, lsmem);
    lstm_kernel<<<128, RT, lsmem>>>(Whh, out, out_size);
}

// round 8
// speedup vs baseline: 1.6581x; 1.0185x over previous
#include <cuda_runtime.h>
#include <cuda_bf16.h>
#include <cstdint>

#define VOCAB 32000
#define EMB   512
#define HID   1024
#define BATCH 32
#define SEQ   512
#define G4    4096
#define NTOK  (BATCH*SEQ)

// ---------------- static device scratch ----------------
__device__ float g_xproj[(size_t)NTOK * G4];            // 256 MB
__device__ uint32_t g_hpk[2][BATCH * HID];              // packed h: lo16=hi(bf16), hi16=lo(bf16)
__device__ __nv_bfloat16 g_embh[(size_t)VOCAB * EMB];   // 32 MB
__device__ __nv_bfloat16 g_embl[(size_t)VOCAB * EMB];
__device__ __nv_bfloat16 g_wihh[(size_t)G4 * EMB];      // 4 MB
__device__ __nv_bfloat16 g_wihl[(size_t)G4 * EMB];
__device__ unsigned g_bar_gen;
__device__ unsigned g_bar_cnt;

// ---------------- helpers ----------------
__device__ __forceinline__ float sigf(float v) { return 1.f / (1.f + __expf(-v)); }

__device__ __forceinline__ uint32_t pkbf(__nv_bfloat16 a, __nv_bfloat16 b) {
    __nv_bfloat162 t; t.x = a; t.y = b;
    return *(uint32_t*)&t;
}

__device__ __forceinline__ void mma_bf16(float c[4], const uint32_t a[4],
                                         uint32_t b0, uint32_t b1) {
    asm volatile(
        "mma.sync.aligned.m16n8k16.row.col.f32.bf16.bf16.f32 "
        "{%0,%1,%2,%3},{%4,%5,%6,%7},{%8,%9},{%0,%1,%2,%3};\n"
        : "+f"(c[0]), "+f"(c[1]), "+f"(c[2]), "+f"(c[3])
        : "r"(a[0]), "r"(a[1]), "r"(a[2]), "r"(a[3]), "r"(b0), "r"(b1));
}

__device__ __forceinline__ void cpa16(uint32_t dst, const void* src) {
    asm volatile("cp.async.cg.shared.global [%0], [%1], 16;" :: "r"(dst), "l"(src));
}
__device__ __forceinline__ void cpa_commit() { asm volatile("cp.async.commit_group;"); }
template<int N>
__device__ __forceinline__ void cpa_wait() { asm volatile("cp.async.wait_group %0;" :: "n"(N)); }

// ---- mbarrier + bulk-copy (UBLKCP) helpers ----
__device__ __forceinline__ void mbar_init(uint32_t mbar, uint32_t count) {
    asm volatile("mbarrier.init.shared.b64 [%0], %1;" :: "r"(mbar), "r"(count));
}
__device__ __forceinline__ void mbar_expect_tx(uint32_t mbar, uint32_t bytes) {
    asm volatile("mbarrier.arrive.expect_tx.shared.b64 _, [%0], %1;"
                 :: "r"(mbar), "r"(bytes) : "memory");
}
__device__ __forceinline__ void bulk_g2s(uint32_t dst, const void* src,
                                         uint32_t bytes, uint32_t mbar) {
    asm volatile(
        "cp.async.bulk.shared::cluster.global.mbarrier::complete_tx::bytes "
        "[%0], [%1], %2, [%3];"
        :: "r"(dst), "l"(src), "r"(bytes), "r"(mbar) : "memory");
}
__device__ __forceinline__ void mbar_wait(uint32_t mbar, uint32_t parity) {
    asm volatile(
        "{\n\t.reg .pred P;\n"
        "WAIT_%=:\n\t"
        "mbarrier.try_wait.parity.acquire.cta.shared::cta.b64 P, [%0], %1, 0x989680;\n\t"
        "@P bra.uni DONE_%=;\n\t"
        "bra.uni WAIT_%=;\n"
        "DONE_%=:\n\t}"
        :: "r"(mbar), "r"(parity) : "memory");
}

__device__ __forceinline__ void grid_barrier(unsigned target) {
    __syncthreads();
    if (threadIdx.x == 0) {
        __threadfence();
        unsigned prev = atomicAdd(&g_bar_cnt, 1u);
        if (prev == gridDim.x - 1) {
            atomicExch(&g_bar_cnt, 0u);
            __threadfence();
            atomicExch(&g_bar_gen, target);
        } else {
            while ((int)(*(volatile unsigned*)&g_bar_gen - target) < 0) { }
        }
        __threadfence();
    }
    __syncthreads();
}

// =====================================================================
// Kernel 0: fp32 -> bf16 hi/lo split planes
// =====================================================================
__global__ void cvt_kernel(const float* __restrict__ src,
                           __nv_bfloat16* __restrict__ hi,
                           __nv_bfloat16* __restrict__ lo, int n4) {
    for (int i = blockIdx.x * blockDim.x + threadIdx.x; i < n4;
         i += gridDim.x * blockDim.x) {
        float4 v = ((const float4*)src)[i];
        __nv_bfloat16 h0 = __float2bfloat16(v.x), h1 = __float2bfloat16(v.y);
        __nv_bfloat16 h2 = __float2bfloat16(v.z), h3 = __float2bfloat16(v.w);
        __nv_bfloat16 l0 = __float2bfloat16(v.x - __bfloat162float(h0));
        __nv_bfloat16 l1 = __float2bfloat16(v.y - __bfloat162float(h1));
        __nv_bfloat16 l2 = __float2bfloat16(v.z - __bfloat162float(h2));
        __nv_bfloat16 l3 = __float2bfloat16(v.w - __bfloat162float(h3));
        ((uint2*)hi)[i] = make_uint2(pkbf(h0, h1), pkbf(h2, h3));
        ((uint2*)lo)[i] = make_uint2(pkbf(l0, l1), pkbf(l2, l3));
    }
}

// =====================================================================
// Kernel 1: x_proj via bf16 split tensor-core GEMM (unchanged).
// =====================================================================
#define XBM 128
#define XBN 128
#define XBK 32
#define XLDA 40
#define XPLANE (XBM * XLDA)
#define XBUF (4 * XPLANE)
#define XKT (EMB / XBK)

__global__ void __launch_bounds__(256, 2) xproj_kernel(
    const int* __restrict__ x,
    const float* __restrict__ bih,
    const float* __restrict__ bhh)
{
    extern __shared__ __nv_bfloat16 xsm[];
    const uint32_t smem_u32 = (uint32_t)__cvta_generic_to_shared(xsm);

    const int tid  = threadIdx.x;
    const int lane = tid & 31;
    const int wid  = tid >> 5;
    const int m0 = blockIdx.y * XBM;
    const int n0 = blockIdx.x * XBN;

    const int lrow = tid >> 1;
    const int lk   = (tid & 1) * 16;
    int erow = x[m0 + lrow];
    erow = max(0, min(VOCAB - 1, erow));
    const __nv_bfloat16* ah_src = g_embh + (size_t)erow * EMB + lk;
    const __nv_bfloat16* al_src = g_embl + (size_t)erow * EMB + lk;
    const __nv_bfloat16* bh_src = g_wihh + (size_t)(n0 + lrow) * EMB + lk;
    const __nv_bfloat16* bl_src = g_wihl + (size_t)(n0 + lrow) * EMB + lk;
    const uint32_t dA = smem_u32 + (uint32_t)(lrow * XLDA + lk) * 2;
    const uint32_t dB = dA + 2 * XPLANE * 2;

    const int wm = (wid >> 2) * 64;
    const int wn = (wid & 3) * 32;
    const int lr = lane >> 2;
    const int lc = lane & 3;

    float acc[4][4][4];
#pragma unroll
    for (int mt = 0; mt < 4; mt++)
#pragma unroll
        for (int nt = 0; nt < 4; nt++)
#pragma unroll
            for (int q = 0; q < 4; q++) acc[mt][nt][q] = 0.f;

    auto issue = [&](int it) {
        const uint32_t bo = (uint32_t)((it & 1) * XBUF) * 2;
        const int ko = it * XBK;
        cpa16(dA + bo,                   ah_src + ko);
        cpa16(dA + bo + 16,              ah_src + ko + 8);
        cpa16(dA + bo + XPLANE * 2,      al_src + ko);
        cpa16(dA + bo + XPLANE * 2 + 16, al_src + ko + 8);
        cpa16(dB + bo,                   bh_src + ko);
        cpa16(dB + bo + 16,              bh_src + ko + 8);
        cpa16(dB + bo + XPLANE * 2,      bl_src + ko);
        cpa16(dB + bo + XPLANE * 2 + 16, bl_src + ko + 8);
    };

    issue(0); cpa_commit();

    for (int it = 0; it < XKT; ++it) {
        if (it < XKT - 1) { issue(it + 1); cpa_commit(); cpa_wait<1>(); }
        else              { cpa_wait<0>(); }
        __syncthreads();

        const __nv_bfloat16* Ah = xsm + (it & 1) * XBUF;
        const __nv_bfloat16* Al = Ah + XPLANE;
        const __nv_bfloat16* Bh = Al + XPLANE;
        const __nv_bfloat16* Bl = Bh + XPLANE;

#pragma unroll
        for (int ksi = 0; ksi < 2; ++ksi) {
            const int ks = ksi * 16;
            uint32_t bfh[4][2], bfl[4][2];
#pragma unroll
            for (int nt = 0; nt < 4; ++nt) {
                const int bi = (wn + nt * 8 + lr) * XLDA + ks + lc * 2;
                bfh[nt][0] = *(const uint32_t*)(Bh + bi);
                bfh[nt][1] = *(const uint32_t*)(Bh + bi + 8);
                bfl[nt][0] = *(const uint32_t*)(Bl + bi);
                bfl[nt][1] = *(const uint32_t*)(Bl + bi + 8);
            }
#pragma unroll
            for (int mt = 0; mt < 4; ++mt) {
                const int ai = (wm + mt * 16 + lr) * XLDA + ks + lc * 2;
                uint32_t afh[4], afl[4];
                afh[0] = *(const uint32_t*)(Ah + ai);
                afh[1] = *(const uint32_t*)(Ah + ai + 8 * XLDA);
                afh[2] = *(const uint32_t*)(Ah + ai + 8);
                afh[3] = *(const uint32_t*)(Ah + ai + 8 * XLDA + 8);
                afl[0] = *(const uint32_t*)(Al + ai);
                afl[1] = *(const uint32_t*)(Al + ai + 8 * XLDA);
                afl[2] = *(const uint32_t*)(Al + ai + 8);
                afl[3] = *(const uint32_t*)(Al + ai + 8 * XLDA + 8);
#pragma unroll
                for (int nt = 0; nt < 4; ++nt) {
                    mma_bf16(acc[mt][nt], afh, bfh[nt][0], bfh[nt][1]);
                    mma_bf16(acc[mt][nt], afh, bfl[nt][0], bfl[nt][1]);
                    mma_bf16(acc[mt][nt], afl, bfh[nt][0], bfh[nt][1]);
                }
            }
        }
        __syncthreads();
    }

    float bias0[4], bias1[4];
#pragma unroll
    for (int nt = 0; nt < 4; ++nt) {
        const int n_g = n0 + wn + nt * 8 + lc * 2;
        bias0[nt] = bih[n_g] + bhh[n_g];
        bias1[nt] = bih[n_g + 1] + bhh[n_g + 1];
    }
#pragma unroll
    for (int mt = 0; mt < 4; ++mt) {
        const int m_g = m0 + wm + mt * 16 + lr;
#pragma unroll
        for (int nt = 0; nt < 4; ++nt) {
            const int n_g = n0 + wn + nt * 8 + lc * 2;
            float2 r0, r1;
            r0.x = acc[mt][nt][0] + bias0[nt];
            r0.y = acc[mt][nt][1] + bias1[nt];
            r1.x = acc[mt][nt][2] + bias0[nt];
            r1.y = acc[mt][nt][3] + bias1[nt];
            *(float2*)&g_xproj[(size_t)m_g * G4 + n_g]       = r0;
            *(float2*)&g_xproj[(size_t)(m_g + 8) * G4 + n_g] = r1;
        }
    }
}

// =====================================================================
// Kernel 2: persistent tensor-core LSTM.
// h broadcast via cp.async.bulk (64 ops/step instead of 8192 LDGSTS).
// Two mbarrier-gated K-half phases; ALL 16 warps compute in each phase
// (K=64 sub-slice per warp per phase).
// =====================================================================
#define RT   512
#define HLD  1036                     // words per h row in smem (4144 B, 16B-mult)
#define RLD  34                       // reduce row pad

__global__ void __launch_bounds__(RT, 1) lstm_kernel(
    const float* __restrict__ Whh,
    float* __restrict__ out,
    int out_size)
{
    extern __shared__ uint32_t lsm[];
    uint32_t* h_s = lsm;                          // [32][HLD]
    float* red = (float*)(lsm + 32 * HLD);        // [8][32][RLD]
    const uint32_t hbase = (uint32_t)__cvta_generic_to_shared(lsm);
    const uint32_t mb0 = hbase + (32 * HLD + 8 * 32 * RLD) * 4;   // 8B aligned
    const uint32_t mb1 = mb0 + 8;

    const int tid  = threadIdx.x;
    const int lane = tid & 31;
    const int wid  = tid >> 5;
    const int kg   = wid >> 1;        // 0..7: K sub-slice index within each half
    const int mt   = wid & 1;         // 0..1 (M-tile of 16)
    const int lr   = lane >> 2;
    const int lc   = lane & 3;
    const int j0   = blockIdx.x * 8;

    const unsigned gen0 = *(volatile unsigned*)&g_bar_gen;

    if (tid == 0) { mbar_init(mb0, 1); mbar_init(mb1, 1); }
    __syncthreads();                 // barriers initialized before any use

    // ---- preload W_hh fragments (registers, resident) ----
    // s=0..3 -> phase0 K = kg*64 + s*16 ; s=4..7 -> phase1 K = 512 + kg*64 + (s-4)*16
    uint32_t ah[8][4], al[8][4];
#pragma unroll
    for (int s = 0; s < 8; ++s) {
        const int kbase = (s < 4) ? (kg * 64 + s * 16) : (512 + kg * 64 + (s - 4) * 16);
#pragma unroll
        for (int r = 0; r < 4; ++r) {
            const int row = mt * 16 + lr + (r & 1) * 8;
            const int kk  = kbase + lc * 2 + (r >> 1) * 8;
            const int q = row >> 3, jl = row & 7;
            float2 w = *(const float2*)(Whh + (size_t)(q * HID + j0 + jl) * HID + kk);
            __nv_bfloat16 h0 = __float2bfloat16(w.x);
            __nv_bfloat16 h1 = __float2bfloat16(w.y);
            __nv_bfloat16 l0 = __float2bfloat16(w.x - __bfloat162float(h0));
            __nv_bfloat16 l1 = __float2bfloat16(w.y - __bfloat162float(h1));
            ah[s][r] = pkbf(h0, h1);
            al[s][r] = pkbf(l0, l1);
        }
    }

    const bool owner = (tid < 256);
    const int b_e  = tid >> 3;
    const int jl_e = tid & 7;
    const int jg   = j0 + jl_e;

    float c_reg = 0.f;
    float xpi = 0.f, xpf = 0.f, xpg = 0.f, xpo = 0.f;

    // ---- t = 0 ----
    if (owner) {
        const float* xp = g_xproj + (size_t)b_e * SEQ * G4;
        float iv = sigf(xp[jg]);
        float gv = tanhf(xp[2 * HID + jg]);
        float ov = sigf(xp[3 * HID + jg]);
        c_reg = iv * gv;
        float hv = ov * tanhf(c_reg);
        out[(size_t)b_e * SEQ * HID + jg] = hv;
        __nv_bfloat16 hh = __float2bfloat16(hv);
        __nv_bfloat16 hl = __float2bfloat16(hv - __bfloat162float(hh));
        g_hpk[1][b_e * HID + jg] = pkbf(hh, hl);
        const float* xp1 = xp + G4;
        xpi = xp1[jg]; xpf = xp1[HID + jg];
        xpg = xp1[2 * HID + jg]; xpo = xp1[3 * HID + jg];
    }
    grid_barrier(gen0 + 1);

    // ---- t = 1 .. 511 ----
    for (int t = 1; t < SEQ; ++t) {
        // ---- broadcast h via bulk copies: 32 rows x (2KB half0 + 2KB half1) ----
        // tid 0..31 are one warp: the tid==0 expect_tx block retires before
        // the tid<32 issue block (intra-warp branch serialization) -> no race.
        if (tid == 0) { mbar_expect_tx(mb0, 65536); mbar_expect_tx(mb1, 65536); }
        if (tid < 32) {
            const char* src = (const char*)g_hpk[t & 1] + (size_t)tid * 4096;
            const uint32_t dst = hbase + (uint32_t)tid * (HLD * 4);
            bulk_g2s(dst,        src,        2048, mb0);   // K[0:512)
            bulk_g2s(dst + 2048, src + 2048, 2048, mb1);   // K[512:1024)
        }
        const uint32_t par = (t - 1) & 1;

        float acc[4][4];
#pragma unroll
        for (int nt = 0; nt < 4; nt++)
#pragma unroll
            for (int q = 0; q < 4; q++) acc[nt][q] = 0.f;

        // ---- phase 0: half0 landed; every warp does its K=64 sub-slice ----
        mbar_wait(mb0, par);
#pragma unroll
        for (int s = 0; s < 4; ++s) {
            const int col = kg * 64 + s * 16 + lc * 2;
#pragma unroll
            for (int nt = 0; nt < 4; ++nt) {
                const uint32_t* hp = h_s + (nt * 8 + lr) * HLD + col;
                uint32_t w0 = hp[0], w1 = hp[1], w2 = hp[8], w3 = hp[9];
                uint32_t bh0 = __byte_perm(w0, w1, 0x5410);
                uint32_t bl0 = __byte_perm(w0, w1, 0x7632);
                uint32_t bh1 = __byte_perm(w2, w3, 0x5410);
                uint32_t bl1 = __byte_perm(w2, w3, 0x7632);
                mma_bf16(acc[nt], ah[s], bh0, bh1);
                mma_bf16(acc[nt], ah[s], bl0, bl1);
                mma_bf16(acc[nt], al[s], bh0, bh1);
            }
        }

        // ---- phase 1: half1 ----
        mbar_wait(mb1, par);
#pragma unroll
        for (int s = 4; s < 8; ++s) {
            const int col = 512 + kg * 64 + (s - 4) * 16 + lc * 2;
#pragma unroll
            for (int nt = 0; nt < 4; ++nt) {
                const uint32_t* hp = h_s + (nt * 8 + lr) * HLD + col;
                uint32_t w0 = hp[0], w1 = hp[1], w2 = hp[8], w3 = hp[9];
                uint32_t bh0 = __byte_perm(w0, w1, 0x5410);
                uint32_t bl0 = __byte_perm(w0, w1, 0x7632);
                uint32_t bh1 = __byte_perm(w2, w3, 0x5410);
                uint32_t bl1 = __byte_perm(w2, w3, 0x7632);
                mma_bf16(acc[nt], ah[s], bh0, bh1);
                mma_bf16(acc[nt], ah[s], bl0, bl1);
                mma_bf16(acc[nt], al[s], bh0, bh1);
            }
        }

        // ---- stage partial sums: red[kg][row][n] ----
#pragma unroll
        for (int nt = 0; nt < 4; ++nt) {
            float* rp = red + (size_t)(kg * 32 + mt * 16 + lr) * RLD + nt * 8 + lc * 2;
            rp[0] = acc[nt][0]; rp[1] = acc[nt][1];
            rp[8 * RLD] = acc[nt][2]; rp[8 * RLD + 1] = acc[nt][3];
        }
        __syncthreads();

        if (owner) {
            float g0 = xpi, g1 = xpf, g2 = xpg, g3 = xpo;
#pragma unroll
            for (int k = 0; k < 8; ++k) {
                const float* rp = red + (size_t)(k * 32 + jl_e) * RLD + b_e;
                g0 += rp[0];
                g1 += rp[8 * RLD];
                g2 += rp[16 * RLD];
                g3 += rp[24 * RLD];
            }
            const float iv = sigf(g0);
            const float fv = sigf(g1);
            const float gv = tanhf(g2);
            const float ov = sigf(g3);
            c_reg = fv * c_reg + iv * gv;
            const float hv = ov * tanhf(c_reg);

            out[((size_t)b_e * SEQ + t) * HID + jg] = hv;
            __nv_bfloat16 hh = __float2bfloat16(hv);
            __nv_bfloat16 hl = __float2bfloat16(hv - __bfloat162float(hh));
            g_hpk[(t + 1) & 1][b_e * HID + jg] = pkbf(hh, hl);

            if (t == SEQ - 1) {
                if (out_size >= NTOK * HID + 2 * BATCH * HID) {
                    float* sh = out + (size_t)NTOK * HID;
                    float* sc = sh + (size_t)BATCH * HID;
                    sh[(size_t)b_e * HID + jg] = hv;
                    sc[(size_t)b_e * HID + jg] = c_reg;
                }
            } else {
                const float* xp = g_xproj + ((size_t)b_e * SEQ + t + 1) * G4;
                xpi = xp[jg]; xpf = xp[HID + jg];
                xpg = xp[2 * HID + jg]; xpo = xp[3 * HID + jg];
            }
        }
        if (t < SEQ - 1) grid_barrier(gen0 + 1 + t);
    }
}

// =====================================================================
extern "C" void kernel_launch(void* const* d_in, const int* in_sizes, int n_in,
                              void* d_out, int out_size)
{
    (void)in_sizes; (void)n_in;
    const int*   x   = (const int*)d_in[0];
    const float* emb = (const float*)d_in[1];
    const float* Wih = (const float*)d_in[2];
    const float* Whh = (const float*)d_in[3];
    const float* bih = (const float*)d_in[4];
    const float* bhh = (const float*)d_in[5];
    float*       out = (float*)d_out;

    static __nv_bfloat16 *p_embh = nullptr, *p_embl, *p_wihh, *p_wihl;
    if (!p_embh) {
        cudaGetSymbolAddress((void**)&p_embh, g_embh);
        cudaGetSymbolAddress((void**)&p_embl, g_embl);
        cudaGetSymbolAddress((void**)&p_wihh, g_wihh);
        cudaGetSymbolAddress((void**)&p_wihl, g_wihl);
    }

    cvt_kernel<<<2048, 256>>>(emb, p_embh, p_embl, VOCAB * EMB / 4);
    cvt_kernel<<<512, 256>>>(Wih, p_wihh, p_wihl, G4 * EMB / 4);

    const int xsmem = 2 * XBUF * (int)sizeof(__nv_bfloat16);            // 81920 B
    cudaFuncSetAttribute(xproj_kernel, cudaFuncAttributeMaxDynamicSharedMemorySize, xsmem);
    dim3 g1(G4 / XBN, NTOK / XBM);
    xproj_kernel<<<g1, 256, xsmem>>>(x, bih, bhh);

    const int lsmem = (32 * HLD + 8 * 32 * RLD) * (int)sizeof(uint32_t) + 16; // 167440 B
    cudaFuncSetAttribute(lstm_kernel, cudaFuncAttributeMaxDynamicSharedMemorySize, lsmem);
    lstm_kernel<<<128, RT, lsmem>>>(Whh, out, out_size);
}